// round 3
// baseline (speedup 1.0000x reference)
#include <cuda_runtime.h>
#include <math.h>

// Problem constants (shapes fixed by dataset: N=10000, E=320000, D 128->128->64)
#define NMAX 10000
#define EMAX 320000

// ---------------- scratch (no allocations allowed) ----------------
__device__ float g_agg[NMAX * 128];
__device__ float g_h1[NMAX * 128];
__device__ float g_h2[NMAX * 64];
__device__ float g_hn[NMAX * 64];
__device__ float g_loss[2];
__device__ int   g_ei[2 * EMAX];    // normalized int32 edge_index
__device__ int   g_nei[2 * EMAX];   // normalized int32 neg_edge_index
__device__ int   g_is64[1];         // dtype flag: 1 if source indices are int64

// ---------------- dtype probe: int64 little-endian -> odd 32-bit words are 0 ----------------
__global__ void detect_idx64(const unsigned* __restrict__ w, int npairs, int* __restrict__ flag) {
    __shared__ unsigned acc;
    if (threadIdx.x == 0) acc = 0u;
    __syncthreads();
    unsigned v = 0u;
    for (int i = threadIdx.x; i < npairs; i += blockDim.x) v |= w[2 * i + 1];
    atomicOr(&acc, v);
    __syncthreads();
    if (threadIdx.x == 0) *flag = (acc == 0u) ? 1 : 0;
}

// ---------------- normalize edge indices to int32 ----------------
__global__ void convert_idx(const void* __restrict__ raw, int n,
                            const int* __restrict__ flag, int* __restrict__ out) {
    int i = blockIdx.x * blockDim.x + threadIdx.x;
    if (i >= n) return;
    if (*flag) out[i] = (int)((const long long*)raw)[i];
    else       out[i] = ((const int*)raw)[i];
}

// ---------------- utility ----------------
__global__ void zero_kernel(float* __restrict__ p, int n) {
    int i = blockIdx.x * blockDim.x + threadIdx.x;
    if (i < n) p[i] = 0.f;
}

// ---------------- edge scatter: agg[dst] += feat[src], D=128 ----------------
__global__ void scatter128(const float4* __restrict__ feat,
                           const int* __restrict__ ei,
                           int E, int N, float* __restrict__ agg) {
    int tid = blockIdx.x * blockDim.x + threadIdx.x;
    int e = tid >> 5;
    if (e >= E) return;
    int c = tid & 31;
    int s = ei[e];
    int d = ei[E + e];
    if ((unsigned)s >= (unsigned)N || (unsigned)d >= (unsigned)N) return;
    float4 v = feat[s * 32 + c];
    float* p = agg + d * 128 + c * 4;
    atomicAdd(p + 0, v.x);
    atomicAdd(p + 1, v.y);
    atomicAdd(p + 2, v.z);
    atomicAdd(p + 3, v.w);
}

// ---------------- fused GraphConv GEMM: out = act(A@W1 + B@W2 + bias) ----------------
template <int C, bool ACT>
__global__ void layer_gemm(const float* __restrict__ A, const float* __restrict__ B,
                           const float* __restrict__ W1, const float* __restrict__ W2,
                           const float* __restrict__ bias, float* __restrict__ out, int N) {
    constexpr int NP = 32 * C / 256;
    __shared__ float As[32][128];
    __shared__ float Bs[32][128];
    int base = blockIdx.x * 32;
    int t = threadIdx.x;
    for (int idx = t; idx < 32 * 128; idx += 256) {
        int n = idx >> 7, k = idx & 127;
        int row = base + n;
        As[n][k] = (row < N) ? A[row * 128 + k] : 0.f;
        Bs[n][k] = (row < N) ? B[row * 128 + k] : 0.f;
    }
    __syncthreads();
    int j = t % C;
    int g = t / C;
    float acc[NP];
#pragma unroll
    for (int n = 0; n < NP; n++) acc[n] = 0.f;
#pragma unroll 4
    for (int k = 0; k < 128; k++) {
        float w1 = W1[k * C + j];
        float w2 = W2[k * C + j];
#pragma unroll
        for (int n = 0; n < NP; n++)
            acc[n] = fmaf(As[g * NP + n][k], w1, fmaf(Bs[g * NP + n][k], w2, acc[n]));
    }
    float bb = bias[j];
#pragma unroll
    for (int n = 0; n < NP; n++) {
        int row = base + g * NP + n;
        if (row < N) {
            float v = acc[n] + bb;
            out[row * C + j] = ACT ? tanhf(v) : v;
        }
    }
}

// ---------------- row normalization (D=64) ----------------
__global__ void normalize64(const float* __restrict__ h2, float* __restrict__ hn, int N) {
    int row = blockIdx.x * 8 + (threadIdx.x >> 5);
    int lane = threadIdx.x & 31;
    if (row >= N) return;
    float a = h2[row * 64 + lane];
    float b = h2[row * 64 + 32 + lane];
    float s = a * a + b * b;
#pragma unroll
    for (int o = 16; o; o >>= 1) s += __shfl_xor_sync(0xffffffffu, s, o);
    float inv = 1.f / fmaxf(sqrtf(s), 1e-8f);
    hn[row * 64 + lane] = a * inv;
    hn[row * 64 + 32 + lane] = b * inv;
}

// ---------------- sim matrix: out[i,j] = sigmoid(hn[i].hn[j]) ----------------
#define SPAD 132
#define SIM_SMEM (2 * 64 * SPAD * 4)

__device__ __forceinline__ float sigm(float x) {
    return 1.f / (1.f + __expf(-x));
}

__global__ void __launch_bounds__(256, 2)
simgemm(const float* __restrict__ hn, float* __restrict__ out, int N) {
    extern __shared__ float sm[];
    float* As = sm;
    float* Bs = sm + 64 * SPAD;
    int bi = blockIdx.y, bj = blockIdx.x;
    int t = threadIdx.x;
    for (int idx = t; idx < 128 * 64; idx += 256) {
        int i = idx >> 6;
        int k = idx & 63;
        int ra = bi * 128 + i;
        int rb = bj * 128 + i;
        As[k * SPAD + i] = (ra < N) ? hn[ra * 64 + k] : 0.f;
        Bs[k * SPAD + i] = (rb < N) ? hn[rb * 64 + k] : 0.f;
    }
    __syncthreads();
    int tx = t & 15, ty = t >> 4;
    float acc[64];
#pragma unroll
    for (int i = 0; i < 64; i++) acc[i] = 0.f;
#pragma unroll 8
    for (int k = 0; k < 64; ++k) {
        const float4* ak = (const float4*)(As + k * SPAD + ty * 8);
        const float4* bk = (const float4*)(Bs + k * SPAD + tx * 8);
        float4 a0 = ak[0], a1 = ak[1];
        float4 b0 = bk[0], b1 = bk[1];
        float a[8] = {a0.x, a0.y, a0.z, a0.w, a1.x, a1.y, a1.z, a1.w};
        float b[8] = {b0.x, b0.y, b0.z, b0.w, b1.x, b1.y, b1.z, b1.w};
#pragma unroll
        for (int r = 0; r < 8; r++)
#pragma unroll
            for (int c = 0; c < 8; c++)
                acc[r * 8 + c] = fmaf(a[r], b[c], acc[r * 8 + c]);
    }
    int i0 = bi * 128 + ty * 8;
    int j0 = bj * 128 + tx * 8;
    if (i0 + 8 <= N && j0 + 8 <= N) {
#pragma unroll
        for (int r = 0; r < 8; r++) {
            size_t base = (size_t)(i0 + r) * (size_t)N + (size_t)j0;
            float4 v0, v1;
            v0.x = sigm(acc[r * 8 + 0]); v0.y = sigm(acc[r * 8 + 1]);
            v0.z = sigm(acc[r * 8 + 2]); v0.w = sigm(acc[r * 8 + 3]);
            v1.x = sigm(acc[r * 8 + 4]); v1.y = sigm(acc[r * 8 + 5]);
            v1.z = sigm(acc[r * 8 + 6]); v1.w = sigm(acc[r * 8 + 7]);
            *(float4*)(out + base) = v0;
            *(float4*)(out + base + 4) = v1;
        }
    } else {
        for (int r = 0; r < 8; r++) {
            int i = i0 + r;
            if (i >= N) break;
            for (int c = 0; c < 8; c++) {
                int j = j0 + c;
                if (j >= N) continue;
                out[(size_t)i * (size_t)N + j] = sigm(acc[r * 8 + c]);
            }
        }
    }
}

// ---------------- edge BCE loss ----------------
__global__ void edge_loss(const float* __restrict__ h, const int* __restrict__ ei,
                          int E, int N, float* __restrict__ loss, int which) {
    int gw = (blockIdx.x * blockDim.x + threadIdx.x) >> 5;
    int lane = threadIdx.x & 31;
    float v = 0.f;
    if (gw < E) {
        int s = ei[gw];
        int d = ei[E + gw];
        if ((unsigned)s < (unsigned)N && (unsigned)d < (unsigned)N) {
            float p = h[s * 64 + lane] * h[d * 64 + lane]
                    + h[s * 64 + 32 + lane] * h[d * 64 + 32 + lane];
#pragma unroll
            for (int o = 16; o; o >>= 1) p += __shfl_xor_sync(0xffffffffu, p, o);
            float z = which ? p : -p;
            v = fmaxf(z, 0.f) + log1pf(expf(-fabsf(z)));
        }
    }
    __shared__ float ws[8];
    if (lane == 0) ws[threadIdx.x >> 5] = v;
    __syncthreads();
    if (threadIdx.x == 0) {
        float s = 0.f;
#pragma unroll
        for (int i = 0; i < 8; i++) s += ws[i];
        atomicAdd(loss + which, s);
    }
}

__global__ void finalize_loss(float* __restrict__ out, const float* __restrict__ loss,
                              int E, int idx) {
    out[idx] = (loss[0] + loss[1]) / (float)E;
}

// ---------------- launch ----------------
extern "C" void kernel_launch(void* const* d_in, const int* in_sizes, int n_in,
                              void* d_out, int out_size) {
    // Input order: [q?], x, edge_index, neg_edge_index, W_rel0, W_root0, b0, W_rel1, W_root1, b1
    int off = (in_sizes[0] <= 1) ? 1 : 0;
    const float* x       = (const float*)d_in[off + 0];
    const void*  ei_raw  = d_in[off + 1];
    const void*  nei_raw = d_in[off + 2];
    const float* W_rel0  = (const float*)d_in[off + 3];
    const float* W_root0 = (const float*)d_in[off + 4];
    const float* b0      = (const float*)d_in[off + 5];
    const float* W_rel1  = (const float*)d_in[off + 6];
    const float* W_root1 = (const float*)d_in[off + 7];
    const float* b1      = (const float*)d_in[off + 8];
    float* out = (float*)d_out;

    int N = in_sizes[off + 0] / 128;
    int E = in_sizes[off + 1] / 2;

    float *agg, *h1, *h2, *hn, *loss;
    int *ei, *nei, *is64;
    cudaGetSymbolAddress((void**)&agg, g_agg);
    cudaGetSymbolAddress((void**)&h1, g_h1);
    cudaGetSymbolAddress((void**)&h2, g_h2);
    cudaGetSymbolAddress((void**)&hn, g_hn);
    cudaGetSymbolAddress((void**)&loss, g_loss);
    cudaGetSymbolAddress((void**)&ei, g_ei);
    cudaGetSymbolAddress((void**)&nei, g_nei);
    cudaGetSymbolAddress((void**)&is64, g_is64);

    // ---- normalize edge index dtype (int32 vs silently-downgraded int64) ----
    int npairs = (2 * E > 8192) ? 4096 : E;  // probe first pairs of 32-bit words
    detect_idx64<<<1, 256>>>((const unsigned*)ei_raw, npairs, is64);
    convert_idx<<<(2 * E + 255) / 256, 256>>>(ei_raw, 2 * E, is64, ei);
    convert_idx<<<(2 * E + 255) / 256, 256>>>(nei_raw, 2 * E, is64, nei);

    // ---- encode layer 0 ----
    zero_kernel<<<(N * 128 + 255) / 256, 256>>>(agg, N * 128);
    zero_kernel<<<1, 32>>>(loss, 2);
    scatter128<<<(E * 32 + 255) / 256, 256>>>((const float4*)x, ei, E, N, agg);
    layer_gemm<128, true><<<(N + 31) / 32, 256>>>(agg, x, W_rel0, W_root0, b0, h1, N);

    // ---- encode layer 1 ----
    zero_kernel<<<(N * 128 + 255) / 256, 256>>>(agg, N * 128);
    scatter128<<<(E * 32 + 255) / 256, 256>>>((const float4*)h1, ei, E, N, agg);
    layer_gemm<64, false><<<(N + 31) / 32, 256>>>(agg, h1, W_rel1, W_root1, b1, h2, N);

    // ---- decode ----
    normalize64<<<(N + 7) / 8, 256>>>(h2, hn, N);
    int nb = (N + 127) / 128;
    cudaFuncSetAttribute(simgemm, cudaFuncAttributeMaxDynamicSharedMemorySize, SIM_SMEM);
    simgemm<<<dim3(nb, nb), 256, SIM_SMEM>>>(hn, out, N);

    // ---- reconstruction loss ----
    edge_loss<<<(E + 7) / 8, 256>>>(h2, ei, E, N, loss, 0);
    edge_loss<<<(E + 7) / 8, 256>>>(h2, nei, E, N, loss, 1);
    if ((long long)out_size > (long long)N * (long long)N)
        finalize_loss<<<1, 1>>>(out, loss, E, out_size - 1);
}

// round 6
// speedup vs baseline: 1.0888x; 1.0888x over previous
#include <cuda_runtime.h>
#include <math.h>

// Problem constants (shapes fixed by dataset: N=10000, E=320000, D 128->128->64)
#define NMAX 10000
#define EMAX 320000

typedef unsigned long long u64;

// ---------------- scratch (no allocations allowed) ----------------
__device__ float g_agg[NMAX * 128];
__device__ float g_h1[NMAX * 128];
__device__ float g_h2[NMAX * 64];
__device__ float g_hn[NMAX * 64];
__device__ float g_loss[2];
__device__ int   g_ei[2 * EMAX];    // normalized int32 edge_index
__device__ int   g_nei[2 * EMAX];   // normalized int32 neg_edge_index
__device__ int   g_is64[1];         // dtype flag: 1 if source indices are int64

// ---------------- dtype probe: int64 little-endian -> odd 32-bit words are 0 ----------------
__global__ void detect_idx64(const unsigned* __restrict__ w, int npairs, int* __restrict__ flag) {
    __shared__ unsigned acc;
    if (threadIdx.x == 0) acc = 0u;
    __syncthreads();
    unsigned v = 0u;
    for (int i = threadIdx.x; i < npairs; i += blockDim.x) v |= w[2 * i + 1];
    atomicOr(&acc, v);
    __syncthreads();
    if (threadIdx.x == 0) *flag = (acc == 0u) ? 1 : 0;
}

// ---------------- normalize edge indices to int32 ----------------
__global__ void convert_idx(const void* __restrict__ raw, int n,
                            const int* __restrict__ flag, int* __restrict__ out) {
    int i = blockIdx.x * blockDim.x + threadIdx.x;
    if (i >= n) return;
    if (*flag) out[i] = (int)((const long long*)raw)[i];
    else       out[i] = ((const int*)raw)[i];
}

// ---------------- utility ----------------
__global__ void zero_kernel(float* __restrict__ p, int n) {
    int i = blockIdx.x * blockDim.x + threadIdx.x;
    if (i < n) p[i] = 0.f;
}

// ---------------- edge scatter: agg[dst] += feat[src], D=128 ----------------
__global__ void scatter128(const float4* __restrict__ feat,
                           const int* __restrict__ ei,
                           int E, int N, float* __restrict__ agg) {
    int tid = blockIdx.x * blockDim.x + threadIdx.x;
    int e = tid >> 5;
    if (e >= E) return;
    int c = tid & 31;
    int s = ei[e];
    int d = ei[E + e];
    if ((unsigned)s >= (unsigned)N || (unsigned)d >= (unsigned)N) return;
    float4 v = feat[s * 32 + c];
    float* p = agg + d * 128 + c * 4;
    atomicAdd(p + 0, v.x);
    atomicAdd(p + 1, v.y);
    atomicAdd(p + 2, v.z);
    atomicAdd(p + 3, v.w);
}

// ---------------- fused GraphConv GEMM: out = act(A@W1 + B@W2 + bias) ----------------
template <int C, bool ACT>
__global__ void layer_gemm(const float* __restrict__ A, const float* __restrict__ B,
                           const float* __restrict__ W1, const float* __restrict__ W2,
                           const float* __restrict__ bias, float* __restrict__ out, int N) {
    constexpr int NP = 32 * C / 256;
    __shared__ float As[32][128];
    __shared__ float Bs[32][128];
    int base = blockIdx.x * 32;
    int t = threadIdx.x;
    for (int idx = t; idx < 32 * 128; idx += 256) {
        int n = idx >> 7, k = idx & 127;
        int row = base + n;
        As[n][k] = (row < N) ? A[row * 128 + k] : 0.f;
        Bs[n][k] = (row < N) ? B[row * 128 + k] : 0.f;
    }
    __syncthreads();
    int j = t % C;
    int g = t / C;
    float acc[NP];
#pragma unroll
    for (int n = 0; n < NP; n++) acc[n] = 0.f;
#pragma unroll 4
    for (int k = 0; k < 128; k++) {
        float w1 = W1[k * C + j];
        float w2 = W2[k * C + j];
#pragma unroll
        for (int n = 0; n < NP; n++)
            acc[n] = fmaf(As[g * NP + n][k], w1, fmaf(Bs[g * NP + n][k], w2, acc[n]));
    }
    float bb = bias[j];
#pragma unroll
    for (int n = 0; n < NP; n++) {
        int row = base + g * NP + n;
        if (row < N) {
            float v = acc[n] + bb;
            out[row * C + j] = ACT ? tanhf(v) : v;
        }
    }
}

// ---------------- row normalization (D=64) ----------------
__global__ void normalize64(const float* __restrict__ h2, float* __restrict__ hn, int N) {
    int row = blockIdx.x * 8 + (threadIdx.x >> 5);
    int lane = threadIdx.x & 31;
    if (row >= N) return;
    float a = h2[row * 64 + lane];
    float b = h2[row * 64 + 32 + lane];
    float s = a * a + b * b;
#pragma unroll
    for (int o = 16; o; o >>= 1) s += __shfl_xor_sync(0xffffffffu, s, o);
    float inv = 1.f / fmaxf(sqrtf(s), 1e-8f);
    hn[row * 64 + lane] = a * inv;
    hn[row * 64 + 32 + lane] = b * inv;
}

// ---------------- sim matrix: out[i,j] = sigmoid(hn[i].hn[j]) ----------------
// Block tile 128x128, 256 threads, 8x8 microtile, K=64 staged in smem.
// Inner product uses Blackwell packed fma.rn.f32x2 (FFMA2): 32 FMA2 + 8 packs
// per k instead of 64 FFMA. Shared layout [k][i], pad 132 (528B rows keep
// 16B alignment for ulonglong2 reads of the B fragment).
#define SPAD 132
#define SIM_SMEM (2 * 64 * SPAD * 4)

// sigmoid via single-MUFU hw tanh: sigmoid(x) = 0.5*tanh(x/2) + 0.5
__device__ __forceinline__ float sigm(float x) {
    float t;
    asm("tanh.approx.f32 %0, %1;" : "=f"(t) : "f"(x * 0.5f));
    return fmaf(0.5f, t, 0.5f);
}

__device__ __forceinline__ u64 dup_f32(float x) {
    u64 r;
    asm("mov.b64 %0, {%1, %1};" : "=l"(r) : "f"(x));
    return r;
}

__device__ __forceinline__ void fma2(u64& d, u64 a, u64 b) {
    asm("fma.rn.f32x2 %0, %1, %2, %0;" : "+l"(d) : "l"(a), "l"(b));
}

__device__ __forceinline__ void unpack2(u64 p, float& lo, float& hi) {
    asm("mov.b64 {%0, %1}, %2;" : "=f"(lo), "=f"(hi) : "l"(p));
}

__global__ void __launch_bounds__(256, 2)
simgemm(const float* __restrict__ hn, float* __restrict__ out, int N) {
    extern __shared__ float sm[];
    float* As = sm;
    float* Bs = sm + 64 * SPAD;
    int bi = blockIdx.y, bj = blockIdx.x;
    int t = threadIdx.x;
    for (int idx = t; idx < 128 * 64; idx += 256) {
        int i = idx >> 6;
        int k = idx & 63;
        int ra = bi * 128 + i;
        int rb = bj * 128 + i;
        As[k * SPAD + i] = (ra < N) ? hn[ra * 64 + k] : 0.f;
        Bs[k * SPAD + i] = (rb < N) ? hn[rb * 64 + k] : 0.f;
    }
    __syncthreads();
    int tx = t & 15, ty = t >> 4;
    // acc[r*4+c] holds packed output pair (col 2c, 2c+1) of row r
    u64 acc[32];
#pragma unroll
    for (int i = 0; i < 32; i++) acc[i] = 0ull;
#pragma unroll 4
    for (int k = 0; k < 64; ++k) {
        const float* arow = As + k * SPAD + ty * 8;
        const float* brow = Bs + k * SPAD + tx * 8;
        float4 a0 = *(const float4*)arow;
        float4 a1 = *(const float4*)(arow + 4);
        ulonglong2 bb0 = *(const ulonglong2*)brow;
        ulonglong2 bb1 = ((const ulonglong2*)brow)[1];
        u64 b[4] = {bb0.x, bb0.y, bb1.x, bb1.y};
        float a[8] = {a0.x, a0.y, a0.z, a0.w, a1.x, a1.y, a1.z, a1.w};
#pragma unroll
        for (int r = 0; r < 8; r++) {
            u64 ar = dup_f32(a[r]);
#pragma unroll
            for (int c = 0; c < 4; c++)
                fma2(acc[r * 4 + c], ar, b[c]);
        }
    }
    int i0 = bi * 128 + ty * 8;
    int j0 = bj * 128 + tx * 8;
    if (i0 + 8 <= N && j0 + 8 <= N) {
#pragma unroll
        for (int r = 0; r < 8; r++) {
            float v[8];
#pragma unroll
            for (int c = 0; c < 4; c++) unpack2(acc[r * 4 + c], v[2 * c], v[2 * c + 1]);
            size_t base = (size_t)(i0 + r) * (size_t)N + (size_t)j0;
            float4 o0, o1;
            o0.x = sigm(v[0]); o0.y = sigm(v[1]); o0.z = sigm(v[2]); o0.w = sigm(v[3]);
            o1.x = sigm(v[4]); o1.y = sigm(v[5]); o1.z = sigm(v[6]); o1.w = sigm(v[7]);
            *(float4*)(out + base) = o0;
            *(float4*)(out + base + 4) = o1;
        }
    } else {
        for (int r = 0; r < 8; r++) {
            int i = i0 + r;
            if (i >= N) break;
            float v[8];
#pragma unroll
            for (int c = 0; c < 4; c++) unpack2(acc[r * 4 + c], v[2 * c], v[2 * c + 1]);
            for (int c = 0; c < 8; c++) {
                int j = j0 + c;
                if (j >= N) continue;
                out[(size_t)i * (size_t)N + j] = sigm(v[c]);
            }
        }
    }
}

// ---------------- edge BCE loss ----------------
__global__ void edge_loss(const float* __restrict__ h, const int* __restrict__ ei,
                          int E, int N, float* __restrict__ loss, int which) {
    int gw = (blockIdx.x * blockDim.x + threadIdx.x) >> 5;
    int lane = threadIdx.x & 31;
    float v = 0.f;
    if (gw < E) {
        int s = ei[gw];
        int d = ei[E + gw];
        if ((unsigned)s < (unsigned)N && (unsigned)d < (unsigned)N) {
            float p = h[s * 64 + lane] * h[d * 64 + lane]
                    + h[s * 64 + 32 + lane] * h[d * 64 + 32 + lane];
#pragma unroll
            for (int o = 16; o; o >>= 1) p += __shfl_xor_sync(0xffffffffu, p, o);
            float z = which ? p : -p;
            v = fmaxf(z, 0.f) + log1pf(expf(-fabsf(z)));
        }
    }
    __shared__ float ws[8];
    if (lane == 0) ws[threadIdx.x >> 5] = v;
    __syncthreads();
    if (threadIdx.x == 0) {
        float s = 0.f;
#pragma unroll
        for (int i = 0; i < 8; i++) s += ws[i];
        atomicAdd(loss + which, s);
    }
}

__global__ void finalize_loss(float* __restrict__ out, const float* __restrict__ loss,
                              int E, int idx) {
    out[idx] = (loss[0] + loss[1]) / (float)E;
}

// ---------------- launch ----------------
extern "C" void kernel_launch(void* const* d_in, const int* in_sizes, int n_in,
                              void* d_out, int out_size) {
    // Input order: [q?], x, edge_index, neg_edge_index, W_rel0, W_root0, b0, W_rel1, W_root1, b1
    int off = (in_sizes[0] <= 1) ? 1 : 0;
    const float* x       = (const float*)d_in[off + 0];
    const void*  ei_raw  = d_in[off + 1];
    const void*  nei_raw = d_in[off + 2];
    const float* W_rel0  = (const float*)d_in[off + 3];
    const float* W_root0 = (const float*)d_in[off + 4];
    const float* b0      = (const float*)d_in[off + 5];
    const float* W_rel1  = (const float*)d_in[off + 6];
    const float* W_root1 = (const float*)d_in[off + 7];
    const float* b1      = (const float*)d_in[off + 8];
    float* out = (float*)d_out;

    int N = in_sizes[off + 0] / 128;
    int E = in_sizes[off + 1] / 2;

    float *agg, *h1, *h2, *hn, *loss;
    int *ei, *nei, *is64;
    cudaGetSymbolAddress((void**)&agg, g_agg);
    cudaGetSymbolAddress((void**)&h1, g_h1);
    cudaGetSymbolAddress((void**)&h2, g_h2);
    cudaGetSymbolAddress((void**)&hn, g_hn);
    cudaGetSymbolAddress((void**)&loss, g_loss);
    cudaGetSymbolAddress((void**)&ei, g_ei);
    cudaGetSymbolAddress((void**)&nei, g_nei);
    cudaGetSymbolAddress((void**)&is64, g_is64);

    // ---- normalize edge index dtype (int32 vs silently-downgraded int64) ----
    int npairs = (2 * E > 8192) ? 4096 : E;
    detect_idx64<<<1, 256>>>((const unsigned*)ei_raw, npairs, is64);
    convert_idx<<<(2 * E + 255) / 256, 256>>>(ei_raw, 2 * E, is64, ei);
    convert_idx<<<(2 * E + 255) / 256, 256>>>(nei_raw, 2 * E, is64, nei);

    // ---- encode layer 0 ----
    zero_kernel<<<(N * 128 + 255) / 256, 256>>>(agg, N * 128);
    zero_kernel<<<1, 32>>>(loss, 2);
    scatter128<<<(E * 32 + 255) / 256, 256>>>((const float4*)x, ei, E, N, agg);
    layer_gemm<128, true><<<(N + 31) / 32, 256>>>(agg, x, W_rel0, W_root0, b0, h1, N);

    // ---- encode layer 1 ----
    zero_kernel<<<(N * 128 + 255) / 256, 256>>>(agg, N * 128);
    scatter128<<<(E * 32 + 255) / 256, 256>>>((const float4*)h1, ei, E, N, agg);
    layer_gemm<64, false><<<(N + 31) / 32, 256>>>(agg, h1, W_rel1, W_root1, b1, h2, N);

    // ---- decode ----
    normalize64<<<(N + 7) / 8, 256>>>(h2, hn, N);
    int nb = (N + 127) / 128;
    cudaFuncSetAttribute(simgemm, cudaFuncAttributeMaxDynamicSharedMemorySize, SIM_SMEM);
    simgemm<<<dim3(nb, nb), 256, SIM_SMEM>>>(hn, out, N);

    // ---- reconstruction loss ----
    edge_loss<<<(E + 7) / 8, 256>>>(h2, ei, E, N, loss, 0);
    edge_loss<<<(E + 7) / 8, 256>>>(h2, nei, E, N, loss, 1);
    if ((long long)out_size > (long long)N * (long long)N)
        finalize_loss<<<1, 1>>>(out, loss, E, out_size - 1);
}

// round 7
// speedup vs baseline: 1.3155x; 1.2082x over previous
#include <cuda_runtime.h>
#include <math.h>

// Problem constants (shapes fixed by dataset: N=10000, E=320000, D 128->128->64)
#define NMAX 10000
#define EMAX 320000

typedef unsigned long long u64;

// ---------------- scratch (no allocations allowed) ----------------
__device__ float g_agg[NMAX * 128];
__device__ float g_h1[NMAX * 128];
__device__ float g_h2[NMAX * 64];
__device__ float g_hn[NMAX * 64];
__device__ float g_loss[2];
__device__ int   g_ei[2 * EMAX];    // normalized int32 edge_index
__device__ int   g_nei[2 * EMAX];   // normalized int32 neg_edge_index
__device__ int   g_is64[1];         // dtype flag: 1 if source indices are int64

// ---------------- dtype probe: int64 little-endian -> odd 32-bit words are 0 ----------------
__global__ void detect_idx64(const unsigned* __restrict__ w, int npairs, int* __restrict__ flag) {
    __shared__ unsigned acc;
    if (threadIdx.x == 0) acc = 0u;
    __syncthreads();
    unsigned v = 0u;
    for (int i = threadIdx.x; i < npairs; i += blockDim.x) v |= w[2 * i + 1];
    atomicOr(&acc, v);
    __syncthreads();
    if (threadIdx.x == 0) *flag = (acc == 0u) ? 1 : 0;
}

// ---------------- normalize edge indices to int32 ----------------
__global__ void convert_idx(const void* __restrict__ raw, int n,
                            const int* __restrict__ flag, int* __restrict__ out) {
    int i = blockIdx.x * blockDim.x + threadIdx.x;
    if (i >= n) return;
    if (*flag) out[i] = (int)((const long long*)raw)[i];
    else       out[i] = ((const int*)raw)[i];
}

// ---------------- utility ----------------
__global__ void zero_kernel(float* __restrict__ p, int n) {
    int i = blockIdx.x * blockDim.x + threadIdx.x;
    if (i < n) p[i] = 0.f;
}

// ---------------- edge scatter: agg[dst] += feat[src], D=128 ----------------
__global__ void scatter128(const float4* __restrict__ feat,
                           const int* __restrict__ ei,
                           int E, int N, float* __restrict__ agg) {
    int tid = blockIdx.x * blockDim.x + threadIdx.x;
    int e = tid >> 5;
    if (e >= E) return;
    int c = tid & 31;
    int s = ei[e];
    int d = ei[E + e];
    if ((unsigned)s >= (unsigned)N || (unsigned)d >= (unsigned)N) return;
    float4 v = feat[s * 32 + c];
    float* p = agg + d * 128 + c * 4;
    atomicAdd(p + 0, v.x);
    atomicAdd(p + 1, v.y);
    atomicAdd(p + 2, v.z);
    atomicAdd(p + 3, v.w);
}

// ---------------- fused GraphConv GEMM: out = act(A@W1 + B@W2 + bias) ----------------
template <int C, bool ACT>
__global__ void layer_gemm(const float* __restrict__ A, const float* __restrict__ B,
                           const float* __restrict__ W1, const float* __restrict__ W2,
                           const float* __restrict__ bias, float* __restrict__ out, int N) {
    constexpr int NP = 32 * C / 256;
    __shared__ float As[32][128];
    __shared__ float Bs[32][128];
    int base = blockIdx.x * 32;
    int t = threadIdx.x;
    for (int idx = t; idx < 32 * 128; idx += 256) {
        int n = idx >> 7, k = idx & 127;
        int row = base + n;
        As[n][k] = (row < N) ? A[row * 128 + k] : 0.f;
        Bs[n][k] = (row < N) ? B[row * 128 + k] : 0.f;
    }
    __syncthreads();
    int j = t % C;
    int g = t / C;
    float acc[NP];
#pragma unroll
    for (int n = 0; n < NP; n++) acc[n] = 0.f;
#pragma unroll 4
    for (int k = 0; k < 128; k++) {
        float w1 = W1[k * C + j];
        float w2 = W2[k * C + j];
#pragma unroll
        for (int n = 0; n < NP; n++)
            acc[n] = fmaf(As[g * NP + n][k], w1, fmaf(Bs[g * NP + n][k], w2, acc[n]));
    }
    float bb = bias[j];
#pragma unroll
    for (int n = 0; n < NP; n++) {
        int row = base + g * NP + n;
        if (row < N) {
            float v = acc[n] + bb;
            out[row * C + j] = ACT ? tanhf(v) : v;
        }
    }
}

// ---------------- row normalization (D=64) ----------------
__global__ void normalize64(const float* __restrict__ h2, float* __restrict__ hn, int N) {
    int row = blockIdx.x * 8 + (threadIdx.x >> 5);
    int lane = threadIdx.x & 31;
    if (row >= N) return;
    float a = h2[row * 64 + lane];
    float b = h2[row * 64 + 32 + lane];
    float s = a * a + b * b;
#pragma unroll
    for (int o = 16; o; o >>= 1) s += __shfl_xor_sync(0xffffffffu, s, o);
    float inv = 1.f / fmaxf(sqrtf(s), 1e-8f);
    hn[row * 64 + lane] = a * inv;
    hn[row * 64 + 32 + lane] = b * inv;
}

// ---------------- sim matrix: out[i,j] = sigmoid(hn[i].hn[j]) ----------------
// Tensor-core version: mma.sync.m16n8k8 tf32. Block tile 128x128, 8 warps,
// warp tile 32(m) x 64(n) = 2 m-tiles x 8 n-tiles of m16n8k8, K=64 (8 k-steps).
// Smem [k][i] with SPAD=136: fragment-load bank = (k*8+row)%32, a perfect
// permutation over (k in 0..3, row in 0..7) -> conflict-free LDS.
#define SPAD 136
#define SIM_SMEM (2 * 64 * SPAD * 4)

// sigmoid via single-MUFU hw tanh: sigmoid(x) = 0.5*tanh(x/2) + 0.5
__device__ __forceinline__ float sigm(float x) {
    float t;
    asm("tanh.approx.f32 %0, %1;" : "=f"(t) : "f"(x * 0.5f));
    return fmaf(0.5f, t, 0.5f);
}

__device__ __forceinline__ void mma_tf32(float* c, const unsigned* a, const unsigned* b) {
    asm volatile(
        "mma.sync.aligned.m16n8k8.row.col.f32.tf32.tf32.f32 "
        "{%0,%1,%2,%3}, {%4,%5,%6,%7}, {%8,%9}, {%0,%1,%2,%3};"
        : "+f"(c[0]), "+f"(c[1]), "+f"(c[2]), "+f"(c[3])
        : "r"(a[0]), "r"(a[1]), "r"(a[2]), "r"(a[3]), "r"(b[0]), "r"(b[1]));
}

__global__ void __launch_bounds__(256, 2)
simgemm(const float* __restrict__ hn, float* __restrict__ out, int N) {
    extern __shared__ float sm[];
    float* As = sm;
    float* Bs = sm + 64 * SPAD;
    const unsigned* Asu = (const unsigned*)As;
    const unsigned* Bsu = (const unsigned*)Bs;
    int bi = blockIdx.y, bj = blockIdx.x;
    int t = threadIdx.x;
    // stage A (rows of block-row bi) and B (rows of block-col bj), layout [k][i]
    for (int idx = t; idx < 128 * 64; idx += 256) {
        int i = idx >> 6;
        int k = idx & 63;
        int ra = bi * 128 + i;
        int rb = bj * 128 + i;
        As[k * SPAD + i] = (ra < N) ? hn[ra * 64 + k] : 0.f;
        Bs[k * SPAD + i] = (rb < N) ? hn[rb * 64 + k] : 0.f;
    }
    __syncthreads();

    int warp = t >> 5;
    int lane = t & 31;
    int mw = warp & 3;        // warp m index: rows mw*32 .. +32
    int nw = warp >> 2;       // warp n index: cols nw*64 .. +64
    int gid = lane >> 2;      // group id 0..7
    int tid4 = lane & 3;      // 0..3

    float c[2][8][4];
#pragma unroll
    for (int mt = 0; mt < 2; mt++)
#pragma unroll
        for (int nt = 0; nt < 8; nt++)
#pragma unroll
            for (int r = 0; r < 4; r++) c[mt][nt][r] = 0.f;

#pragma unroll
    for (int ks = 0; ks < 8; ks++) {
        int k0 = ks * 8;
        // A fragments: a[mt] = {A[r,c], A[r+8,c], A[r,c+4], A[r+8,c+4]}
        unsigned a[2][4];
#pragma unroll
        for (int mt = 0; mt < 2; mt++) {
            int row = mw * 32 + mt * 16 + gid;
            a[mt][0] = Asu[(k0 + tid4) * SPAD + row];
            a[mt][1] = Asu[(k0 + tid4) * SPAD + row + 8];
            a[mt][2] = Asu[(k0 + 4 + tid4) * SPAD + row];
            a[mt][3] = Asu[(k0 + 4 + tid4) * SPAD + row + 8];
        }
        // B fragments: b[nt] = {B[k,n], B[k+4,n]}  (col-major k x n)
        unsigned b[8][2];
#pragma unroll
        for (int nt = 0; nt < 8; nt++) {
            int col = nw * 64 + nt * 8 + gid;
            b[nt][0] = Bsu[(k0 + tid4) * SPAD + col];
            b[nt][1] = Bsu[(k0 + 4 + tid4) * SPAD + col];
        }
#pragma unroll
        for (int mt = 0; mt < 2; mt++)
#pragma unroll
            for (int nt = 0; nt < 8; nt++)
                mma_tf32(c[mt][nt], a[mt], b[nt]);
    }

    // epilogue: c[mt][nt] covers rows {r0, r0+8}, cols {c0, c0+1} with
    // r0 = mw*32 + mt*16 + gid, c0 = nw*64 + nt*8 + tid4*2
    int i_base = bi * 128 + mw * 32;
    int j_base = bj * 128 + nw * 64;
    bool interior = (bi * 128 + 128 <= N) && (bj * 128 + 128 <= N);
    if (interior) {
#pragma unroll
        for (int mt = 0; mt < 2; mt++) {
#pragma unroll
            for (int h = 0; h < 2; h++) {
                int row = i_base + mt * 16 + h * 8 + gid;
                size_t rbase = (size_t)row * (size_t)N + (size_t)(j_base + tid4 * 2);
#pragma unroll
                for (int nt = 0; nt < 8; nt++) {
                    float2 v;
                    v.x = sigm(c[mt][nt][h * 2 + 0]);
                    v.y = sigm(c[mt][nt][h * 2 + 1]);
                    *(float2*)(out + rbase + nt * 8) = v;
                }
            }
        }
    } else {
        for (int mt = 0; mt < 2; mt++) {
            for (int h = 0; h < 2; h++) {
                int row = i_base + mt * 16 + h * 8 + gid;
                if (row >= N) continue;
                for (int nt = 0; nt < 8; nt++) {
                    int col = j_base + nt * 8 + tid4 * 2;
                    if (col < N)
                        out[(size_t)row * (size_t)N + col] = sigm(c[mt][nt][h * 2 + 0]);
                    if (col + 1 < N)
                        out[(size_t)row * (size_t)N + col + 1] = sigm(c[mt][nt][h * 2 + 1]);
                }
            }
        }
    }
}

// ---------------- edge BCE loss ----------------
__global__ void edge_loss(const float* __restrict__ h, const int* __restrict__ ei,
                          int E, int N, float* __restrict__ loss, int which) {
    int gw = (blockIdx.x * blockDim.x + threadIdx.x) >> 5;
    int lane = threadIdx.x & 31;
    float v = 0.f;
    if (gw < E) {
        int s = ei[gw];
        int d = ei[E + gw];
        if ((unsigned)s < (unsigned)N && (unsigned)d < (unsigned)N) {
            float p = h[s * 64 + lane] * h[d * 64 + lane]
                    + h[s * 64 + 32 + lane] * h[d * 64 + 32 + lane];
#pragma unroll
            for (int o = 16; o; o >>= 1) p += __shfl_xor_sync(0xffffffffu, p, o);
            float z = which ? p : -p;
            v = fmaxf(z, 0.f) + log1pf(expf(-fabsf(z)));
        }
    }
    __shared__ float ws[8];
    if (lane == 0) ws[threadIdx.x >> 5] = v;
    __syncthreads();
    if (threadIdx.x == 0) {
        float s = 0.f;
#pragma unroll
        for (int i = 0; i < 8; i++) s += ws[i];
        atomicAdd(loss + which, s);
    }
}

__global__ void finalize_loss(float* __restrict__ out, const float* __restrict__ loss,
                              int E, int idx) {
    out[idx] = (loss[0] + loss[1]) / (float)E;
}

// ---------------- launch ----------------
extern "C" void kernel_launch(void* const* d_in, const int* in_sizes, int n_in,
                              void* d_out, int out_size) {
    // Input order: [q?], x, edge_index, neg_edge_index, W_rel0, W_root0, b0, W_rel1, W_root1, b1
    int off = (in_sizes[0] <= 1) ? 1 : 0;
    const float* x       = (const float*)d_in[off + 0];
    const void*  ei_raw  = d_in[off + 1];
    const void*  nei_raw = d_in[off + 2];
    const float* W_rel0  = (const float*)d_in[off + 3];
    const float* W_root0 = (const float*)d_in[off + 4];
    const float* b0      = (const float*)d_in[off + 5];
    const float* W_rel1  = (const float*)d_in[off + 6];
    const float* W_root1 = (const float*)d_in[off + 7];
    const float* b1      = (const float*)d_in[off + 8];
    float* out = (float*)d_out;

    int N = in_sizes[off + 0] / 128;
    int E = in_sizes[off + 1] / 2;

    float *agg, *h1, *h2, *hn, *loss;
    int *ei, *nei, *is64;
    cudaGetSymbolAddress((void**)&agg, g_agg);
    cudaGetSymbolAddress((void**)&h1, g_h1);
    cudaGetSymbolAddress((void**)&h2, g_h2);
    cudaGetSymbolAddress((void**)&hn, g_hn);
    cudaGetSymbolAddress((void**)&loss, g_loss);
    cudaGetSymbolAddress((void**)&ei, g_ei);
    cudaGetSymbolAddress((void**)&nei, g_nei);
    cudaGetSymbolAddress((void**)&is64, g_is64);

    // ---- normalize edge index dtype (int32 vs silently-downgraded int64) ----
    int npairs = (2 * E > 8192) ? 4096 : E;
    detect_idx64<<<1, 256>>>((const unsigned*)ei_raw, npairs, is64);
    convert_idx<<<(2 * E + 255) / 256, 256>>>(ei_raw, 2 * E, is64, ei);
    convert_idx<<<(2 * E + 255) / 256, 256>>>(nei_raw, 2 * E, is64, nei);

    // ---- encode layer 0 ----
    zero_kernel<<<(N * 128 + 255) / 256, 256>>>(agg, N * 128);
    zero_kernel<<<1, 32>>>(loss, 2);
    scatter128<<<(E * 32 + 255) / 256, 256>>>((const float4*)x, ei, E, N, agg);
    layer_gemm<128, true><<<(N + 31) / 32, 256>>>(agg, x, W_rel0, W_root0, b0, h1, N);

    // ---- encode layer 1 ----
    zero_kernel<<<(N * 128 + 255) / 256, 256>>>(agg, N * 128);
    scatter128<<<(E * 32 + 255) / 256, 256>>>((const float4*)h1, ei, E, N, agg);
    layer_gemm<64, false><<<(N + 31) / 32, 256>>>(agg, h1, W_rel1, W_root1, b1, h2, N);

    // ---- decode ----
    normalize64<<<(N + 7) / 8, 256>>>(h2, hn, N);
    int nb = (N + 127) / 128;
    cudaFuncSetAttribute(simgemm, cudaFuncAttributeMaxDynamicSharedMemorySize, SIM_SMEM);
    simgemm<<<dim3(nb, nb), 256, SIM_SMEM>>>(hn, out, N);

    // ---- reconstruction loss ----
    edge_loss<<<(E + 7) / 8, 256>>>(h2, ei, E, N, loss, 0);
    edge_loss<<<(E + 7) / 8, 256>>>(h2, nei, E, N, loss, 1);
    if ((long long)out_size > (long long)N * (long long)N)
        finalize_loss<<<1, 1>>>(out, loss, E, out_size - 1);
}